// round 7
// baseline (speedup 1.0000x reference)
#include <cuda_runtime.h>
#include <cstdint>

// ---------------- problem constants ----------------
#define TOKS   32768
#define DIMD   128
#define KCB    8192
#define TM     128              // tokens per CTA
#define NQ     8                // codebook slices (wave balance: 2048 CTAs)
#define QCODES (KCB / NQ)       // 1024
#define CHUNK  128              // codes per B chunk
#define NCHUNK (QCODES / CHUNK) // 8
#define NTILES (TOKS / TM)      // 256
#define BIAS   512.0f
#define TAU    0.55f            // rescore window (includes quant slack)

#define A_BYTES      32768                  // packed A: 8 mb * 8 ks * 32 lanes * 16B
#define BSTAGE_BYTES 32768                  // packed B chunk
#define STG_FLOATS   (128 * 132)            // raw fp32 staging (padded rows)
#define SMEM_TOTAL   (A_BYTES + STG_FLOATS * 4)   // 100352

__device__ float g_cnorm[KCB];              // raw ||c||^2 (rescore)
__device__ float g_cnormb[KCB];             // ||c||^2 + BIAS (fold)
__device__ uint4 g_cb_pk[(KCB / 8) * 4 * 32];  // fragment-packed bf16 codebook (2MB)
__device__ float g_bestd[NQ * TOKS * 2];    // per-slice screened top-2
__device__ int   g_besti[NQ * TOKS * 2];
__device__ int   g_idx[TOKS];               // final winners

// ---------------- PTX helpers (baseline sm_80+) ----------------
__device__ __forceinline__ uint32_t bf16x2(float hi, float lo) {
    uint32_t r;
    asm("cvt.rn.bf16x2.f32 %0, %1, %2;" : "=r"(r) : "f"(hi), "f"(lo));
    return r;
}
__device__ __forceinline__ void cp_async16(uint32_t saddr, const void* gptr) {
    asm volatile("cp.async.cg.shared.global [%0], [%1], 16;"
                 :: "r"(saddr), "l"(gptr) : "memory");
}
#define CP_COMMIT() asm volatile("cp.async.commit_group;" ::: "memory")
#define CP_WAIT1()  asm volatile("cp.async.wait_group 1;" ::: "memory")
#define CP_WAIT0()  asm volatile("cp.async.wait_group 0;" ::: "memory")

__device__ __forceinline__ void mma_bf16(float* d, uint4 a,
                                         uint32_t b0, uint32_t b1) {
    asm volatile(
        "mma.sync.aligned.m16n8k16.row.col.f32.bf16.bf16.f32 "
        "{%0,%1,%2,%3}, {%4,%5,%6,%7}, {%8,%9}, {%0,%1,%2,%3};"
        : "+f"(d[0]), "+f"(d[1]), "+f"(d[2]), "+f"(d[3])
        : "r"(a.x), "r"(a.y), "r"(a.z), "r"(a.w), "r"(b0), "r"(b1));
}

__device__ __forceinline__ void ins2(uint32_t& a, uint32_t& b, uint32_t u) {
    uint32_t mx = a > u ? a : u;
    a = a < u ? a : u;
    b = b < mx ? b : mx;
}
__device__ __forceinline__ bool cmpdc(float d1, int c1, float d2, int c2) {
    return d1 < d2 || (d1 == d2 && c1 < c2);
}
__device__ __forceinline__ void merge2(float& a1, int& i1, float& a2, int& i2,
                                       float b1, int j1, float b2, int j2) {
    bool t = cmpdc(a1, i1, b1, j1);
    float m1 = t ? a1 : b1;  int mi1 = t ? i1 : j1;
    float x1 = t ? b1 : a1;  int xi1 = t ? j1 : i1;
    float x2 = t ? a2 : b2;  int xi2 = t ? i2 : j2;
    bool t2 = cmpdc(x2, xi2, x1, xi1);
    a1 = m1; i1 = mi1;
    a2 = t2 ? x2 : x1; i2 = t2 ? xi2 : xi1;
}

// ---------------- prep: fragment-packed bf16 codebook + norms (fused) ----------------
__global__ __launch_bounds__(256) void prep_kernel(const float* __restrict__ cb) {
    int nb = (blockIdx.x * blockDim.x + threadIdx.x) >> 5;
    int lane = threadIdx.x & 31;
    if (nb >= KCB / 8) return;
    int g = lane >> 2, tg = lane & 3;
    const float* row = cb + (size_t)(nb * 8 + g) * DIMD;
    float s = 0.f;
#pragma unroll
    for (int ks2 = 0; ks2 < 4; ++ks2) {
        int k0 = ks2 * 32;
        float2 a = *(const float2*)&row[k0 + 2 * tg];
        float2 b = *(const float2*)&row[k0 + 8 + 2 * tg];
        float2 c = *(const float2*)&row[k0 + 16 + 2 * tg];
        float2 d = *(const float2*)&row[k0 + 24 + 2 * tg];
        s = fmaf(a.x, a.x, s); s = fmaf(a.y, a.y, s);
        s = fmaf(b.x, b.x, s); s = fmaf(b.y, b.y, s);
        s = fmaf(c.x, c.x, s); s = fmaf(c.y, c.y, s);
        s = fmaf(d.x, d.x, s); s = fmaf(d.y, d.y, s);
        uint4 u;
        u.x = bf16x2(a.y, a.x); u.y = bf16x2(b.y, b.x);
        u.z = bf16x2(c.y, c.x); u.w = bf16x2(d.y, d.x);
        g_cb_pk[((size_t)nb * 4 + ks2) * 32 + lane] = u;
    }
    s += __shfl_xor_sync(0xffffffffu, s, 1);
    s += __shfl_xor_sync(0xffffffffu, s, 2);
    if (tg == 0) {
        g_cnorm[nb * 8 + g] = s;
        g_cnormb[nb * 8 + g] = s + BIAS;
    }
}

// ---------------- main VQ kernel: bf16 screening, packed-uint top-2 ----------------
__global__ __launch_bounds__(256, 2) void vq_kernel(const float* __restrict__ ze)
{
    extern __shared__ char smem[];
    uint4* Apk = (uint4*)smem;
    float* stg = (float*)(smem + A_BYTES);

    const int t      = threadIdx.x;
    const int lane   = t & 31;
    const int wid    = t >> 5;
    const int g      = lane >> 2;
    const int tg     = lane & 3;
    const int warp_m = wid >> 2;
    const int warp_n = wid & 3;

    const int tile  = blockIdx.x >> 3;
    const int q     = blockIdx.x & 7;
    const int tok0  = tile * TM;
    const int cbase = q * QCODES;

    // ---- stage raw ze tile ----
    {
        uint32_t sb = (uint32_t)__cvta_generic_to_shared(stg);
#pragma unroll
        for (int i = 0; i < 16; ++i) {
            int f = t + i * 256;
            int r = f >> 5, c4 = f & 31;
            cp_async16(sb + (uint32_t)(r * 132 + c4 * 4) * 4,
                       ze + (size_t)(tok0 + r) * DIMD + c4 * 4);
        }
        CP_COMMIT(); CP_WAIT0();
    }
    __syncthreads();

    // ---- pack A = bf16(-2*ze) into fragment order ----
    {
        const int mb = wid;
        const int r0 = mb * 16 + g, r1 = r0 + 8;
#pragma unroll
        for (int ks = 0; ks < 8; ++ks) {
            int c0 = ks * 16 + 2 * tg, c1 = c0 + 8;
            float2 v00 = *(const float2*)&stg[r0 * 132 + c0];
            float2 v10 = *(const float2*)&stg[r1 * 132 + c0];
            float2 v01 = *(const float2*)&stg[r0 * 132 + c1];
            float2 v11 = *(const float2*)&stg[r1 * 132 + c1];
            uint4 u;
            u.x = bf16x2(-2.f * v00.y, -2.f * v00.x);
            u.y = bf16x2(-2.f * v10.y, -2.f * v10.x);
            u.z = bf16x2(-2.f * v01.y, -2.f * v01.x);
            u.w = bf16x2(-2.f * v11.y, -2.f * v11.x);
            Apk[(mb * 8 + ks) * 32 + lane] = u;
        }
    }
    __syncthreads();

    // ---- prefetch B chunk 0 ----
    {
        uint32_t bb = (uint32_t)__cvta_generic_to_shared(smem + A_BYTES);
        const char* src = (const char*)&g_cb_pk[((size_t)cbase >> 3) * 4 * 32];
#pragma unroll
        for (int i = 0; i < 8; ++i)
            cp_async16(bb + (uint32_t)(i * 256 + t) * 16, src + (i * 256 + t) * 16);
        CP_COMMIT();
    }

    uint32_t top1[8], top2v[8];
#pragma unroll
    for (int s = 0; s < 8; ++s) { top1[s] = 0xFFFFFFFFu; top2v[s] = 0xFFFFFFFFu; }

    const uint32_t MASK = 0xFFFFFFC0u;   // 6-bit local id (64 ids: 8 ch * 8)

    for (int ch = 0; ch < NCHUNK; ++ch) {
        if (ch + 1 < NCHUNK) {
            uint32_t bb = (uint32_t)__cvta_generic_to_shared(
                smem + A_BYTES + ((ch + 1) & 1) * BSTAGE_BYTES);
            const char* src = (const char*)
                &g_cb_pk[((size_t)(cbase + (ch + 1) * CHUNK) >> 3) * 4 * 32];
#pragma unroll
            for (int i = 0; i < 8; ++i)
                cp_async16(bb + (uint32_t)(i * 256 + t) * 16,
                           src + (i * 256 + t) * 16);
            CP_COMMIT(); CP_WAIT1();
        } else {
            CP_WAIT0();
        }
        __syncthreads();

        const uint4* bs = (const uint4*)(smem + A_BYTES + (ch & 1) * BSTAGE_BYTES);

        float acc[4][4][4];
#pragma unroll
        for (int mt = 0; mt < 4; ++mt)
#pragma unroll
            for (int nt = 0; nt < 4; ++nt)
#pragma unroll
                for (int r = 0; r < 4; ++r) acc[mt][nt][r] = 0.f;

#pragma unroll
        for (int ks2 = 0; ks2 < 4; ++ks2) {
            uint4 B4[4];
#pragma unroll
            for (int nt = 0; nt < 4; ++nt)
                B4[nt] = bs[(((warp_n * 4 + nt) * 4) + ks2) * 32 + lane];
            uint4 A4[4];
#pragma unroll
            for (int mt = 0; mt < 4; ++mt)
                A4[mt] = Apk[((warp_m * 4 + mt) * 8 + 2 * ks2) * 32 + lane];
#pragma unroll
            for (int mt = 0; mt < 4; ++mt)
#pragma unroll
                for (int nt = 0; nt < 4; ++nt)
                    mma_bf16(acc[mt][nt], A4[mt], B4[nt].x, B4[nt].y);
#pragma unroll
            for (int mt = 0; mt < 4; ++mt)
                A4[mt] = Apk[((warp_m * 4 + mt) * 8 + 2 * ks2 + 1) * 32 + lane];
#pragma unroll
            for (int mt = 0; mt < 4; ++mt)
#pragma unroll
                for (int nt = 0; nt < 4; ++nt)
                    mma_bf16(acc[mt][nt], A4[mt], B4[nt].z, B4[nt].w);
        }

        // ---- branchless fold: pack (d2+BIAS, 6-bit local id) into uint ----
#pragma unroll
        for (int nt = 0; nt < 4; ++nt) {
            int cg = cbase + ch * CHUNK + warp_n * 32 + nt * 8 + 2 * tg;
            float cn0 = __ldg(&g_cnormb[cg]);
            float cn1 = __ldg(&g_cnormb[cg + 1]);
            uint32_t lidb = (uint32_t)(ch * 8 + nt * 2);
#pragma unroll
            for (int mt = 0; mt < 4; ++mt) {
                int s0 = mt * 2, s1 = s0 + 1;
                uint32_t u;
                u = (__float_as_uint(acc[mt][nt][0] + cn0) & MASK) | lidb;
                ins2(top1[s0], top2v[s0], u);
                u = (__float_as_uint(acc[mt][nt][1] + cn1) & MASK) | (lidb + 1);
                ins2(top1[s0], top2v[s0], u);
                u = (__float_as_uint(acc[mt][nt][2] + cn0) & MASK) | lidb;
                ins2(top1[s1], top2v[s1], u);
                u = (__float_as_uint(acc[mt][nt][3] + cn1) & MASK) | (lidb + 1);
                ins2(top1[s1], top2v[s1], u);
            }
        }
        __syncthreads();
    }

    // ---- decode + reduce across tg (shfl) and warp_n (smem) ----
    float* rv = (float*)smem;
    int*   ri = (int*)(smem + 4096);

#pragma unroll
    for (int s = 0; s < 8; ++s) {
        float d1 = __uint_as_float(top1[s] & MASK);
        float d2 = __uint_as_float(top2v[s] & MASK);
        int l1 = (int)(top1[s] & 63u), l2 = (int)(top2v[s] & 63u);
        int c1 = cbase + (l1 >> 3) * CHUNK + warp_n * 32 + ((l1 >> 1) & 3) * 8
               + 2 * tg + (l1 & 1);
        int c2 = cbase + (l2 >> 3) * CHUNK + warp_n * 32 + ((l2 >> 1) & 3) * 8
               + 2 * tg + (l2 & 1);
#pragma unroll
        for (int off = 1; off < 4; off <<= 1) {
            float od1 = __shfl_xor_sync(0xffffffffu, d1, off);
            float od2 = __shfl_xor_sync(0xffffffffu, d2, off);
            int   oc1 = __shfl_xor_sync(0xffffffffu, c1, off);
            int   oc2 = __shfl_xor_sync(0xffffffffu, c2, off);
            merge2(d1, c1, d2, c2, od1, oc1, od2, oc2);
        }
        if (tg == 0) {
            int mt = s >> 1, half = s & 1;
            int row = warp_m * 64 + mt * 16 + g + half * 8;
            rv[row * 8 + warp_n * 2 + 0] = d1;
            rv[row * 8 + warp_n * 2 + 1] = d2;
            ri[row * 8 + warp_n * 2 + 0] = c1;
            ri[row * 8 + warp_n * 2 + 1] = c2;
        }
    }
    __syncthreads();

    if (t < TM) {
        float d1 = rv[t * 8 + 0], d2 = rv[t * 8 + 1];
        int   c1 = ri[t * 8 + 0], c2 = ri[t * 8 + 1];
#pragma unroll
        for (int w = 1; w < 4; ++w)
            merge2(d1, c1, d2, c2,
                   rv[t * 8 + w * 2], ri[t * 8 + w * 2],
                   rv[t * 8 + w * 2 + 1], ri[t * 8 + w * 2 + 1]);
        size_t base = ((size_t)q * TOKS + tok0 + t) * 2;
        g_bestd[base + 0] = d1; g_bestd[base + 1] = d2;
        g_besti[base + 0] = c1; g_besti[base + 1] = c2;
    }
}

// ---------------- merge slices + exact rescore (thread per token) ----------------
__global__ __launch_bounds__(256) void merge_kernel(
    const float* __restrict__ ze, const float* __restrict__ cb,
    float* __restrict__ out, int out_size)
{
    int tok = blockIdx.x * 256 + threadIdx.x;
    if (tok >= TOKS) return;

    float cv[NQ * 2]; int ci[NQ * 2];
#pragma unroll
    for (int qq = 0; qq < NQ; ++qq) {
        size_t base = ((size_t)qq * TOKS + tok) * 2;
        cv[qq * 2 + 0] = g_bestd[base + 0]; ci[qq * 2 + 0] = g_besti[base + 0];
        cv[qq * 2 + 1] = g_bestd[base + 1]; ci[qq * 2 + 1] = g_besti[base + 1];
    }
    float b1v = cv[0]; int b1i = ci[0];
#pragma unroll
    for (int j = 1; j < NQ * 2; ++j)
        if (cmpdc(cv[j], ci[j], b1v, b1i)) { b1v = cv[j]; b1i = ci[j]; }
    int nwin = 0;
#pragma unroll
    for (int j = 0; j < NQ * 2; ++j)
        if (cv[j] <= b1v + TAU) ++nwin;

    int winner = b1i;
    if (nwin > 1) {
        const float4* xr = (const float4*)(ze + (size_t)tok * DIMD);
        float bd = 3.4e38f; int bi = 0x7fffffff;
#pragma unroll 1
        for (int j = 0; j < NQ * 2; ++j) {
            if (cv[j] > b1v + TAU) continue;
            int c = ci[j];
            const float4* cr = (const float4*)(cb + (size_t)c * DIMD);
            float dot = 0.f;
#pragma unroll
            for (int k = 0; k < 32; ++k) {
                float4 a = xr[k], b = cr[k];
                dot = fmaf(a.x, b.x, dot);
                dot = fmaf(a.y, b.y, dot);
                dot = fmaf(a.z, b.z, dot);
                dot = fmaf(a.w, b.w, dot);
            }
            float d2 = fmaf(-2.f, dot, __ldg(&g_cnorm[c]));
            if (d2 < bd || (d2 == bd && c < bi)) { bd = d2; bi = c; }
        }
        winner = bi;
    }
    g_idx[tok] = winner;
    if (out_size > TOKS * DIMD)
        out[(size_t)TOKS * DIMD + tok] = (float)winner;
}

// ---------------- gather: warp per token (broadcast idx, coalesced copy) --------
__global__ __launch_bounds__(256) void gather_kernel(
    const float* __restrict__ cb, float* __restrict__ out)
{
    int gid  = blockIdx.x * 256 + threadIdx.x;   // one float4 per thread
    int tok  = gid >> 5;
    int lane = gid & 31;
    int idx  = __ldg(&g_idx[tok]);
    ((float4*)out)[gid] = ((const float4*)cb)[(size_t)idx * 32 + lane];
}

extern "C" void kernel_launch(void* const* d_in, const int* in_sizes, int n_in,
                              void* d_out, int out_size) {
    const float* ze = (const float*)d_in[0];
    const float* cb = (const float*)d_in[1];
    if (n_in >= 2 && in_sizes[0] == KCB * DIMD && in_sizes[1] == TOKS * DIMD) {
        const float* tmp = ze; ze = cb; cb = tmp;
    }

    cudaFuncSetAttribute(vq_kernel, cudaFuncAttributeMaxDynamicSharedMemorySize,
                         SMEM_TOTAL);

    prep_kernel<<<(KCB / 8) * 32 / 256, 256>>>(cb);
    vq_kernel<<<NTILES * NQ, 256, SMEM_TOTAL>>>(ze);
    merge_kernel<<<TOKS / 256, 256>>>(ze, cb, (float*)d_out, out_size);
    gather_kernel<<<TOKS * 32 / 256, 256>>>(cb, (float*)d_out);
}

// round 8
// speedup vs baseline: 1.0906x; 1.0906x over previous
#include <cuda_runtime.h>
#include <cstdint>

// ---------------- problem constants ----------------
#define TOKS   32768
#define DIMD   128
#define KCB    8192
#define TM     128              // tokens per CTA
#define NQ     4                // codebook slices (1024 CTAs)
#define QCODES (KCB / NQ)       // 2048
#define CHUNK  128              // codes per B chunk
#define NCHUNK (QCODES / CHUNK) // 16
#define NTILES (TOKS / TM)      // 256
#define BIAS   512.0f
#define TAU    0.55f            // rescore window (includes quant slack)

#define A_BYTES      32768      // packed A: 8 mb * 8 ks * 32 lanes * 16B
#define BSTAGE_BYTES 32768      // packed B chunk
#define SMEM_TOTAL   (A_BYTES + 2 * BSTAGE_BYTES)   // 98304

__device__ float g_cnorm[KCB];              // raw ||c||^2 (rescore)
__device__ float g_cnormb[KCB];             // ||c||^2 + BIAS (fold)
__device__ uint4 g_cb_pk[(KCB / 8) * 4 * 32];  // fragment-packed bf16 codebook
__device__ float g_bestd[NQ * TOKS * 2];    // per-slice screened top-2
__device__ int   g_besti[NQ * TOKS * 2];
__device__ int   g_idx[TOKS];               // final winners

// ---------------- PTX helpers (baseline sm_80+) ----------------
__device__ __forceinline__ uint32_t bf16x2(float hi, float lo) {
    uint32_t r;
    asm("cvt.rn.bf16x2.f32 %0, %1, %2;" : "=r"(r) : "f"(hi), "f"(lo));
    return r;
}
__device__ __forceinline__ void cp_async16(uint32_t saddr, const void* gptr) {
    asm volatile("cp.async.cg.shared.global [%0], [%1], 16;"
                 :: "r"(saddr), "l"(gptr) : "memory");
}
#define CP_COMMIT() asm volatile("cp.async.commit_group;" ::: "memory")
#define CP_WAIT1()  asm volatile("cp.async.wait_group 1;" ::: "memory")
#define CP_WAIT0()  asm volatile("cp.async.wait_group 0;" ::: "memory")

__device__ __forceinline__ void mma_bf16(float* d, uint4 a,
                                         uint32_t b0, uint32_t b1) {
    asm volatile(
        "mma.sync.aligned.m16n8k16.row.col.f32.bf16.bf16.f32 "
        "{%0,%1,%2,%3}, {%4,%5,%6,%7}, {%8,%9}, {%0,%1,%2,%3};"
        : "+f"(d[0]), "+f"(d[1]), "+f"(d[2]), "+f"(d[3])
        : "r"(a.x), "r"(a.y), "r"(a.z), "r"(a.w), "r"(b0), "r"(b1));
}

__device__ __forceinline__ void ins2(uint32_t& a, uint32_t& b, uint32_t u) {
    uint32_t mx = a > u ? a : u;
    a = a < u ? a : u;
    b = b < mx ? b : mx;
}
__device__ __forceinline__ bool cmpdc(float d1, int c1, float d2, int c2) {
    return d1 < d2 || (d1 == d2 && c1 < c2);
}
__device__ __forceinline__ void merge2(float& a1, int& i1, float& a2, int& i2,
                                       float b1, int j1, float b2, int j2) {
    bool t = cmpdc(a1, i1, b1, j1);
    float m1 = t ? a1 : b1;  int mi1 = t ? i1 : j1;
    float x1 = t ? b1 : a1;  int xi1 = t ? j1 : i1;
    float x2 = t ? a2 : b2;  int xi2 = t ? i2 : j2;
    bool t2 = cmpdc(x2, xi2, x1, xi1);
    a1 = m1; i1 = mi1;
    a2 = t2 ? x2 : x1; i2 = t2 ? xi2 : xi1;
}

// ---------------- prep: fragment-packed bf16 codebook + norms (fused) ----------------
__global__ __launch_bounds__(256) void prep_kernel(const float* __restrict__ cb) {
    int nb = (blockIdx.x * blockDim.x + threadIdx.x) >> 5;
    int lane = threadIdx.x & 31;
    if (nb >= KCB / 8) return;
    int g = lane >> 2, tg = lane & 3;
    const float* row = cb + (size_t)(nb * 8 + g) * DIMD;
    float s = 0.f;
#pragma unroll
    for (int ks2 = 0; ks2 < 4; ++ks2) {
        int k0 = ks2 * 32;
        float2 a = *(const float2*)&row[k0 + 2 * tg];
        float2 b = *(const float2*)&row[k0 + 8 + 2 * tg];
        float2 c = *(const float2*)&row[k0 + 16 + 2 * tg];
        float2 d = *(const float2*)&row[k0 + 24 + 2 * tg];
        s = fmaf(a.x, a.x, s); s = fmaf(a.y, a.y, s);
        s = fmaf(b.x, b.x, s); s = fmaf(b.y, b.y, s);
        s = fmaf(c.x, c.x, s); s = fmaf(c.y, c.y, s);
        s = fmaf(d.x, d.x, s); s = fmaf(d.y, d.y, s);
        uint4 u;
        u.x = bf16x2(a.y, a.x); u.y = bf16x2(b.y, b.x);
        u.z = bf16x2(c.y, c.x); u.w = bf16x2(d.y, d.x);
        g_cb_pk[((size_t)nb * 4 + ks2) * 32 + lane] = u;
    }
    s += __shfl_xor_sync(0xffffffffu, s, 1);
    s += __shfl_xor_sync(0xffffffffu, s, 2);
    if (tg == 0) {
        g_cnorm[nb * 8 + g] = s;
        g_cnormb[nb * 8 + g] = s + BIAS;
    }
}

// ---------------- main VQ kernel: bf16 screening, packed-uint top-2 ----------------
__global__ __launch_bounds__(256, 2) void vq_kernel(const float* __restrict__ ze)
{
    extern __shared__ char smem[];
    uint4* Apk = (uint4*)smem;

    const int t      = threadIdx.x;
    const int lane   = t & 31;
    const int wid    = t >> 5;
    const int g      = lane >> 2;
    const int tg     = lane & 3;
    const int warp_m = wid >> 2;
    const int warp_n = wid & 3;

    const int tile  = blockIdx.x >> 2;
    const int q     = blockIdx.x & 3;
    const int tok0  = tile * TM;
    const int cbase = q * QCODES;

    // ---- issue B chunk-0 prefetch FIRST (overlaps all of A pack) ----
    {
        uint32_t bb = (uint32_t)__cvta_generic_to_shared(smem + A_BYTES);
        const char* src = (const char*)&g_cb_pk[((size_t)cbase >> 3) * 4 * 32];
#pragma unroll
        for (int i = 0; i < 8; ++i)
            cp_async16(bb + (uint32_t)(i * 256 + t) * 16, src + (i * 256 + t) * 16);
        CP_COMMIT();
    }

    // ---- pack A = bf16(-2*ze) in fragment order via DIRECT LDG (no staging) ----
    {
        const int mb = wid;
        const float* r0p = ze + (size_t)(tok0 + mb * 16 + g) * DIMD;
        const float* r1p = r0p + 8 * DIMD;
#pragma unroll
        for (int ks = 0; ks < 8; ++ks) {
            int c0 = ks * 16 + 2 * tg, c1 = c0 + 8;
            float2 v00 = *(const float2*)&r0p[c0];
            float2 v10 = *(const float2*)&r1p[c0];
            float2 v01 = *(const float2*)&r0p[c1];
            float2 v11 = *(const float2*)&r1p[c1];
            uint4 u;
            u.x = bf16x2(-2.f * v00.y, -2.f * v00.x);
            u.y = bf16x2(-2.f * v10.y, -2.f * v10.x);
            u.z = bf16x2(-2.f * v01.y, -2.f * v01.x);
            u.w = bf16x2(-2.f * v11.y, -2.f * v11.x);
            Apk[(mb * 8 + ks) * 32 + lane] = u;
        }
    }
    __syncthreads();

    uint32_t top1[8], top2v[8];
#pragma unroll
    for (int s = 0; s < 8; ++s) { top1[s] = 0xFFFFFFFFu; top2v[s] = 0xFFFFFFFFu; }

    const uint32_t MASK = 0xFFFFFF80u;   // 7-bit local id (128 ids: 16 ch * 8)

    for (int ch = 0; ch < NCHUNK; ++ch) {
        if (ch + 1 < NCHUNK) {
            uint32_t bb = (uint32_t)__cvta_generic_to_shared(
                smem + A_BYTES + ((ch + 1) & 1) * BSTAGE_BYTES);
            const char* src = (const char*)
                &g_cb_pk[((size_t)(cbase + (ch + 1) * CHUNK) >> 3) * 4 * 32];
#pragma unroll
            for (int i = 0; i < 8; ++i)
                cp_async16(bb + (uint32_t)(i * 256 + t) * 16,
                           src + (i * 256 + t) * 16);
            CP_COMMIT(); CP_WAIT1();
        } else {
            CP_WAIT0();
        }
        __syncthreads();

        const uint4* bs = (const uint4*)(smem + A_BYTES + (ch & 1) * BSTAGE_BYTES);

        float acc[4][4][4];
#pragma unroll
        for (int mt = 0; mt < 4; ++mt)
#pragma unroll
            for (int nt = 0; nt < 4; ++nt)
#pragma unroll
                for (int r = 0; r < 4; ++r) acc[mt][nt][r] = 0.f;

#pragma unroll
        for (int ks2 = 0; ks2 < 4; ++ks2) {
            uint4 B4[4];
#pragma unroll
            for (int nt = 0; nt < 4; ++nt)
                B4[nt] = bs[(((warp_n * 4 + nt) * 4) + ks2) * 32 + lane];
            uint4 A4[4];
#pragma unroll
            for (int mt = 0; mt < 4; ++mt)
                A4[mt] = Apk[((warp_m * 4 + mt) * 8 + 2 * ks2) * 32 + lane];
#pragma unroll
            for (int mt = 0; mt < 4; ++mt)
#pragma unroll
                for (int nt = 0; nt < 4; ++nt)
                    mma_bf16(acc[mt][nt], A4[mt], B4[nt].x, B4[nt].y);
#pragma unroll
            for (int mt = 0; mt < 4; ++mt)
                A4[mt] = Apk[((warp_m * 4 + mt) * 8 + 2 * ks2 + 1) * 32 + lane];
#pragma unroll
            for (int mt = 0; mt < 4; ++mt)
#pragma unroll
                for (int nt = 0; nt < 4; ++nt)
                    mma_bf16(acc[mt][nt], A4[mt], B4[nt].z, B4[nt].w);
        }

        // ---- branchless fold: pack (d2+BIAS, 7-bit local id) into uint ----
#pragma unroll
        for (int nt = 0; nt < 4; ++nt) {
            int cg = cbase + ch * CHUNK + warp_n * 32 + nt * 8 + 2 * tg;
            float cn0 = __ldg(&g_cnormb[cg]);
            float cn1 = __ldg(&g_cnormb[cg + 1]);
            uint32_t lidb = (uint32_t)(ch * 8 + nt * 2);
#pragma unroll
            for (int mt = 0; mt < 4; ++mt) {
                int s0 = mt * 2, s1 = s0 + 1;
                uint32_t u;
                u = (__float_as_uint(acc[mt][nt][0] + cn0) & MASK) | lidb;
                ins2(top1[s0], top2v[s0], u);
                u = (__float_as_uint(acc[mt][nt][1] + cn1) & MASK) | (lidb + 1);
                ins2(top1[s0], top2v[s0], u);
                u = (__float_as_uint(acc[mt][nt][2] + cn0) & MASK) | lidb;
                ins2(top1[s1], top2v[s1], u);
                u = (__float_as_uint(acc[mt][nt][3] + cn1) & MASK) | (lidb + 1);
                ins2(top1[s1], top2v[s1], u);
            }
        }
        __syncthreads();
    }

    // ---- decode + reduce across tg (shfl) and warp_n (smem) ----
    float* rv = (float*)smem;
    int*   ri = (int*)(smem + 4096);

#pragma unroll
    for (int s = 0; s < 8; ++s) {
        float d1 = __uint_as_float(top1[s] & MASK);
        float d2 = __uint_as_float(top2v[s] & MASK);
        int l1 = (int)(top1[s] & 127u), l2 = (int)(top2v[s] & 127u);
        int c1 = cbase + (l1 >> 3) * CHUNK + warp_n * 32 + ((l1 >> 1) & 3) * 8
               + 2 * tg + (l1 & 1);
        int c2 = cbase + (l2 >> 3) * CHUNK + warp_n * 32 + ((l2 >> 1) & 3) * 8
               + 2 * tg + (l2 & 1);
#pragma unroll
        for (int off = 1; off < 4; off <<= 1) {
            float od1 = __shfl_xor_sync(0xffffffffu, d1, off);
            float od2 = __shfl_xor_sync(0xffffffffu, d2, off);
            int   oc1 = __shfl_xor_sync(0xffffffffu, c1, off);
            int   oc2 = __shfl_xor_sync(0xffffffffu, c2, off);
            merge2(d1, c1, d2, c2, od1, oc1, od2, oc2);
        }
        if (tg == 0) {
            int mt = s >> 1, half = s & 1;
            int row = warp_m * 64 + mt * 16 + g + half * 8;
            rv[row * 8 + warp_n * 2 + 0] = d1;
            rv[row * 8 + warp_n * 2 + 1] = d2;
            ri[row * 8 + warp_n * 2 + 0] = c1;
            ri[row * 8 + warp_n * 2 + 1] = c2;
        }
    }
    __syncthreads();

    if (t < TM) {
        float d1 = rv[t * 8 + 0], d2 = rv[t * 8 + 1];
        int   c1 = ri[t * 8 + 0], c2 = ri[t * 8 + 1];
#pragma unroll
        for (int w = 1; w < 4; ++w)
            merge2(d1, c1, d2, c2,
                   rv[t * 8 + w * 2], ri[t * 8 + w * 2],
                   rv[t * 8 + w * 2 + 1], ri[t * 8 + w * 2 + 1]);
        size_t base = ((size_t)q * TOKS + tok0 + t) * 2;
        g_bestd[base + 0] = d1; g_bestd[base + 1] = d2;
        g_besti[base + 0] = c1; g_besti[base + 1] = c2;
    }
}

// ---------------- merge slices + exact rescore (thread per token) ----------------
__global__ __launch_bounds__(256) void merge_kernel(
    const float* __restrict__ ze, const float* __restrict__ cb,
    float* __restrict__ out, int out_size)
{
    int tok = blockIdx.x * 256 + threadIdx.x;
    if (tok >= TOKS) return;

    float cv[NQ * 2]; int ci[NQ * 2];
#pragma unroll
    for (int qq = 0; qq < NQ; ++qq) {
        size_t base = ((size_t)qq * TOKS + tok) * 2;
        cv[qq * 2 + 0] = g_bestd[base + 0]; ci[qq * 2 + 0] = g_besti[base + 0];
        cv[qq * 2 + 1] = g_bestd[base + 1]; ci[qq * 2 + 1] = g_besti[base + 1];
    }
    float b1v = cv[0]; int b1i = ci[0];
#pragma unroll
    for (int j = 1; j < NQ * 2; ++j)
        if (cmpdc(cv[j], ci[j], b1v, b1i)) { b1v = cv[j]; b1i = ci[j]; }
    int nwin = 0;
#pragma unroll
    for (int j = 0; j < NQ * 2; ++j)
        if (cv[j] <= b1v + TAU) ++nwin;

    int winner = b1i;
    if (nwin > 1) {
        const float4* xr = (const float4*)(ze + (size_t)tok * DIMD);
        float bd = 3.4e38f; int bi = 0x7fffffff;
#pragma unroll 1
        for (int j = 0; j < NQ * 2; ++j) {
            if (cv[j] > b1v + TAU) continue;
            int c = ci[j];
            const float4* cr = (const float4*)(cb + (size_t)c * DIMD);
            float dot = 0.f;
#pragma unroll
            for (int k = 0; k < 32; ++k) {
                float4 a = xr[k], b = cr[k];
                dot = fmaf(a.x, b.x, dot);
                dot = fmaf(a.y, b.y, dot);
                dot = fmaf(a.z, b.z, dot);
                dot = fmaf(a.w, b.w, dot);
            }
            float d2 = fmaf(-2.f, dot, __ldg(&g_cnorm[c]));
            if (d2 < bd || (d2 == bd && c < bi)) { bd = d2; bi = c; }
        }
        winner = bi;
    }
    g_idx[tok] = winner;
    if (out_size > TOKS * DIMD)
        out[(size_t)TOKS * DIMD + tok] = (float)winner;
}

// ---------------- gather: warp per token (broadcast idx, coalesced copy) --------
__global__ __launch_bounds__(256) void gather_kernel(
    const float* __restrict__ cb, float* __restrict__ out)
{
    int gid  = blockIdx.x * 256 + threadIdx.x;   // one float4 per thread
    int tok  = gid >> 5;
    int lane = gid & 31;
    int idx  = __ldg(&g_idx[tok]);
    ((float4*)out)[gid] = ((const float4*)cb)[(size_t)idx * 32 + lane];
}

extern "C" void kernel_launch(void* const* d_in, const int* in_sizes, int n_in,
                              void* d_out, int out_size) {
    const float* ze = (const float*)d_in[0];
    const float* cb = (const float*)d_in[1];
    if (n_in >= 2 && in_sizes[0] == KCB * DIMD && in_sizes[1] == TOKS * DIMD) {
        const float* tmp = ze; ze = cb; cb = tmp;
    }

    cudaFuncSetAttribute(vq_kernel, cudaFuncAttributeMaxDynamicSharedMemorySize,
                         SMEM_TOTAL);

    prep_kernel<<<(KCB / 8) * 32 / 256, 256>>>(cb);
    vq_kernel<<<NTILES * NQ, 256, SMEM_TOTAL>>>(ze);
    merge_kernel<<<TOKS / 256, 256>>>(ze, cb, (float*)d_out, out_size);
    gather_kernel<<<TOKS * 32 / 256, 256>>>(cb, (float*)d_out);
}